// round 11
// baseline (speedup 1.0000x reference)
#include <cuda_runtime.h>
#include <cuda_fp16.h>
#include <cstdint>

// ---------------------------------------------------------------------------
// InteractionPPBlock (DimeNet++) — round 11: barrier-free register-resident
// triplet scatter + pre-transformed basis; GEMMs as in R10
// ---------------------------------------------------------------------------

#define H 256
#define INTC 64
#define SBF_DIM 42
#define NRAD 6
#define BAS 8

#define MAXE 200704
#define MAXT 2000000
#define MAXE_H ((size_t)MAXE * H)
#define MAXE_I ((size_t)MAXE * INTC)

__device__ float g_buf0[MAXE_H];
__device__ float g_buf1[MAXE_H];
__device__ float g_down[MAXE_I];
__device__ float g_agg[MAXE_I];
__device__ float g_Wr[NRAD * H];
__device__ float g_sb2[(size_t)MAXT * BAS];
__device__ __half g_P0h[MAXE_H], g_P0l[MAXE_H];
__device__ __half g_P1h[MAXE_H], g_P1l[MAXE_H];
__device__ __half g_P2h[MAXE_H], g_P2l[MAXE_H];
__device__ __half g_aggh[MAXE_I], g_aggl[MAXE_I];
__device__ __half g_Wsp[22 * 65536];

__device__ __forceinline__ float silu(float v) {
    return v / (1.0f + __expf(-v));
}
__device__ __forceinline__ void h_split(float v, __half& h, __half& l) {
    h = __float2half_rn(v);
    l = __float2half_rn(v - __half2float(h));
}

__device__ __forceinline__ void mma_f16(float* d, const uint32_t* a, const uint32_t* b) {
    asm volatile(
        "mma.sync.aligned.m16n8k16.row.col.f32.f16.f16.f32 "
        "{%0,%1,%2,%3},{%4,%5,%6,%7},{%8,%9},{%0,%1,%2,%3};\n"
        : "+f"(d[0]), "+f"(d[1]), "+f"(d[2]), "+f"(d[3])
        : "r"(a[0]), "r"(a[1]), "r"(a[2]), "r"(a[3]), "r"(b[0]), "r"(b[1]));
}
__device__ __forceinline__ void ldsm_x4(uint32_t* r, uint32_t addr) {
    asm volatile("ldmatrix.sync.aligned.m8n8.x4.shared.b16 {%0,%1,%2,%3}, [%4];"
                 : "=r"(r[0]), "=r"(r[1]), "=r"(r[2]), "=r"(r[3]) : "r"(addr));
}

__device__ __forceinline__ uint32_t smem_u32(const void* p) {
    uint32_t a;
    asm("{ .reg .u64 t; cvta.to.shared.u64 t, %1; cvt.u32.u64 %0, t; }" : "=r"(a) : "l"(p));
    return a;
}
__device__ __forceinline__ void cp_async16(uint32_t dst, const void* src, int szr) {
    asm volatile("cp.async.cg.shared.global [%0], [%1], 16, %2;"
                 :: "r"(dst), "l"(src), "r"(szr) : "memory");
}
#define CP_COMMIT() asm volatile("cp.async.commit_group;" ::: "memory")
#define CP_WAIT(n)  asm volatile("cp.async.wait_group %0;" :: "n"(n) : "memory")

// ---------------------------------------------------------------------------
// GEMM (identical to R10): BM=128, BN=32*NBLK, BK=16, 256 thr, 4 stages
// ---------------------------------------------------------------------------
#define BM 128
#define STAGES 4

template <int NK, int NCBLK, int NBLK>
__global__ void __launch_bounds__(256, 2) gemm_f16x2(
    const __half* __restrict__ Ah, const __half* __restrict__ Al,
    const __half* __restrict__ Bh, const __half* __restrict__ Bl,
    const float* __restrict__ bias, const float* __restrict__ mul,
    const float* __restrict__ addF,
    const __half* __restrict__ addH, const __half* __restrict__ addL,
    float* __restrict__ Cf, __half* __restrict__ Chi, __half* __restrict__ Clo,
    int M, int N) {

    constexpr int NT   = NBLK * 2;
    constexpr int BSTG = NBLK * 1024;
    constexpr int STG  = 12288 + 2 * BSTG;
    constexpr int BN   = NBLK * 32;
    constexpr int K    = NK * 16;

    extern __shared__ char smem_raw[];
    char* bp = smem_raw;
    const uint32_t s0 = smem_u32(smem_raw);

    const int tid  = threadIdx.x;
    const int wid  = tid >> 5;
    const int lane = tid & 31;
    const int g    = lane >> 2;
    const int t    = lane & 3;
    const int wy   = wid >> 1;
    const int wx   = wid & 1;

    const int rowBase = blockIdx.x * BM;
    const int colBase = blockIdx.y * BN;
    const int cblk0   = colBase >> 5;

    const int ar = tid >> 1, ac = tid & 1;
    const int gr = rowBase + ar;
    const bool aV = gr < M;
    const __half* aSrcH = Ah + (size_t)(aV ? gr : 0) * K + ac * 8;
    const __half* aSrcL = Al + (size_t)(aV ? gr : 0) * K + ac * 8;
    const uint32_t aDstH = s0 + (uint32_t)(ar * 48 + ac * 16);
    const uint32_t aDstL = aDstH + 6144u;
    constexpr int bStep = NCBLK * 512;

    int bChunk;
    const __half* bSrc0;
    const __half* bSrc1;
    uint32_t bDst0, bDst1;
    if (NBLK == 4) {
        bChunk = tid;
        const int cblkL = bChunk >> 6, rr = (bChunk >> 5) & 1, bln = bChunk & 31;
        const size_t off = ((size_t)((cblk0 + cblkL) * 2 + rr) * 32 + bln) * 8;
        bSrc0 = Bh + off;
        bSrc1 = Bl + off;
        bDst0 = s0 + 12288u + (uint32_t)bChunk * 16;
        bDst1 = bDst0 + (uint32_t)BSTG;
    } else {
        bChunk = tid & 127;
        const int cblkL = bChunk >> 6, rr = (bChunk >> 5) & 1, bln = bChunk & 31;
        const size_t off = ((size_t)((cblk0 + cblkL) * 2 + rr) * 32 + bln) * 8;
        bSrc0 = ((tid < 128) ? Bh : Bl) + off;
        bSrc1 = nullptr;
        bDst0 = s0 + 12288u + (tid < 128 ? 0u : (uint32_t)BSTG) + (uint32_t)bChunk * 16;
        bDst1 = 0;
    }

    const uint32_t lds_a_off =
        (uint32_t)(((lane & 7) + ((lane >> 3) & 1) * 8) * 48 + ((lane >> 4) & 1) * 16);

    float acc[2][NT][4];
    #pragma unroll
    for (int i = 0; i < 2; i++)
        #pragma unroll
        for (int j = 0; j < NT; j++)
            #pragma unroll
            for (int r = 0; r < 4; r++) acc[i][j][r] = 0.f;

    #pragma unroll
    for (int s = 0; s < STAGES - 1; s++) {
        if (s < NK) {
            cp_async16(aDstH + s * STG, aSrcH + s * 16, aV ? 16 : 0);
            cp_async16(aDstL + s * STG, aSrcL + s * 16, aV ? 16 : 0);
            cp_async16(bDst0 + s * STG, bSrc0 + (size_t)s * bStep, 16);
            if (NBLK == 4)
                cp_async16(bDst1 + s * STG, bSrc1 + (size_t)s * bStep, 16);
        }
        CP_COMMIT();
    }

    #pragma unroll
    for (int it = 0; it < NK; ++it) {
        const int pend = NK - 1 - it;
        if (pend >= 2)      CP_WAIT(2);
        else if (pend == 1) CP_WAIT(1);
        else                CP_WAIT(0);
        __syncthreads();

        const int nx = it + STAGES - 1;
        if (nx < NK) {
            const uint32_t so = (uint32_t)(nx % STAGES) * STG;
            cp_async16(aDstH + so, aSrcH + nx * 16, aV ? 16 : 0);
            cp_async16(aDstL + so, aSrcL + nx * 16, aV ? 16 : 0);
            cp_async16(bDst0 + so, bSrc0 + (size_t)nx * bStep, 16);
            if (NBLK == 4)
                cp_async16(bDst1 + so, bSrc1 + (size_t)nx * bStep, 16);
            CP_COMMIT();
        }

        const uint32_t sb = (uint32_t)(it % STAGES) * STG;
        const uint32_t bHiBase = sb + 12288u;
        const uint32_t bLoBase = bHiBase + (uint32_t)BSTG;

        uint32_t ah[2][4], al[2][4];
        #pragma unroll
        for (int mt = 0; mt < 2; mt++) {
            const int m0 = wy * 32 + mt * 16;
            ldsm_x4(ah[mt], s0 + sb + (uint32_t)(m0 * 48) + lds_a_off);
            ldsm_x4(al[mt], s0 + sb + 6144u + (uint32_t)(m0 * 48) + lds_a_off);
        }

        uint32_t bh[NT][2];
        #pragma unroll
        for (int j = 0; j < NBLK / 2; j++) {
            const int cb = wx * (NBLK / 2) + j;
            uint4 v0 = *reinterpret_cast<uint4*>(bp + bHiBase + ((cb * 2 + 0) * 32 + lane) * 16);
            uint4 v1 = *reinterpret_cast<uint4*>(bp + bHiBase + ((cb * 2 + 1) * 32 + lane) * 16);
            bh[j * 4 + 0][0] = v0.x; bh[j * 4 + 1][0] = v0.y;
            bh[j * 4 + 2][0] = v0.z; bh[j * 4 + 3][0] = v0.w;
            bh[j * 4 + 0][1] = v1.x; bh[j * 4 + 1][1] = v1.y;
            bh[j * 4 + 2][1] = v1.z; bh[j * 4 + 3][1] = v1.w;
        }

        #pragma unroll
        for (int mt = 0; mt < 2; mt++)
            #pragma unroll
            for (int nt = 0; nt < NT; nt++)
                mma_f16(acc[mt][nt], al[mt], bh[nt]);

        uint32_t bl[NT][2];
        #pragma unroll
        for (int j = 0; j < NBLK / 2; j++) {
            const int cb = wx * (NBLK / 2) + j;
            uint4 v0 = *reinterpret_cast<uint4*>(bp + bLoBase + ((cb * 2 + 0) * 32 + lane) * 16);
            uint4 v1 = *reinterpret_cast<uint4*>(bp + bLoBase + ((cb * 2 + 1) * 32 + lane) * 16);
            bl[j * 4 + 0][0] = v0.x; bl[j * 4 + 1][0] = v0.y;
            bl[j * 4 + 2][0] = v0.z; bl[j * 4 + 3][0] = v0.w;
            bl[j * 4 + 0][1] = v1.x; bl[j * 4 + 1][1] = v1.y;
            bl[j * 4 + 2][1] = v1.z; bl[j * 4 + 3][1] = v1.w;
        }

        #pragma unroll
        for (int mt = 0; mt < 2; mt++)
            #pragma unroll
            for (int nt = 0; nt < NT; nt++)
                mma_f16(acc[mt][nt], ah[mt], bl[nt]);

        #pragma unroll
        for (int mt = 0; mt < 2; mt++)
            #pragma unroll
            for (int nt = 0; nt < NT; nt++)
                mma_f16(acc[mt][nt], ah[mt], bh[nt]);
    }

    #pragma unroll
    for (int mt = 0; mt < 2; mt++) {
        #pragma unroll
        for (int nt = 0; nt < NT; nt++) {
            const int c0 = colBase + wx * (NT * 8) + nt * 8 + 2 * t;
            if (c0 >= N) continue;
            #pragma unroll
            for (int half = 0; half < 2; half++) {
                const int row = rowBase + wy * 32 + mt * 16 + g + 8 * half;
                if (row >= M) continue;
                const size_t idx = (size_t)row * N + c0;
                float v0 = acc[mt][nt][half * 2];
                float v1 = acc[mt][nt][half * 2 + 1];
                if (bias) { v0 += bias[c0]; v1 += bias[c0 + 1]; }
                v0 = silu(v0); v1 = silu(v1);
                if (mul)  { v0 *= mul[idx];  v1 *= mul[idx + 1]; }
                if (addF) { v0 += addF[idx]; v1 += addF[idx + 1]; }
                if (addH) {
                    v0 += __half2float(addH[idx]) + __half2float(addL[idx]);
                    v1 += __half2float(addH[idx + 1]) + __half2float(addL[idx + 1]);
                }
                if (Cf) { Cf[idx] = v0; Cf[idx + 1] = v1; }
                if (Chi) {
                    __half h0, l0, h1, l1;
                    h_split(v0, h0, l0); h_split(v1, h1, l1);
                    *reinterpret_cast<__half2*>(Chi + idx) = __halves2half2(h0, h1);
                    *reinterpret_cast<__half2*>(Clo + idx) = __halves2half2(l0, l1);
                }
            }
        }
    }
}

// ---------------------------------------------------------------------------
// Prep kernels (unchanged)
// ---------------------------------------------------------------------------
__global__ void split_w_kernel(
    const float* p0, const float* p1, const float* p2, const float* p3,
    const float* p4, const float* p5, const float* p6, const float* p7,
    const float* p8, const float* p9, const float* p10) {
    const float* srcs[11] = {p0, p1, p2, p3, p4, p5, p6, p7, p8, p9, p10};
    const int KK[11]  = {256, 256, 256, 64, 256, 256, 256, 256, 256, 256, 256};
    const int NN[11]  = {256, 256, 64, 256, 256, 256, 256, 256, 256, 256, 256};
    const int NC[11]  = {8, 8, 4, 8, 8, 8, 8, 8, 8, 8, 8};
    const int w = blockIdx.y;
    const int i = blockIdx.x * 256 + threadIdx.x;
    const int K = KK[w], N = NN[w], ncblk = NC[w];
    const int total = (K / 16) * ncblk * 256;
    if (i >= total) return;
    const int kb = i / (ncblk * 256);
    const int rem = i % (ncblk * 256);
    const int cblk = rem >> 8;
    const int j = rem & 255;
    const int r = j >> 7, lane = (j >> 2) & 31, nt = j & 3;
    const int gg = lane >> 2, tt = lane & 3;
    const int k0 = kb * 16 + r * 8 + tt * 2;
    const int n  = cblk * 32 + nt * 8 + gg;
    const float* W = srcs[w];
    float v0 = (n < N && k0 < K)     ? W[(size_t)k0 * N + n]       : 0.f;
    float v1 = (n < N && k0 + 1 < K) ? W[(size_t)(k0 + 1) * N + n] : 0.f;
    __half h0, l0, h1, l1;
    h_split(v0, h0, l0); h_split(v1, h1, l1);
    const size_t o = (size_t)i * 2;
    __half* hi = g_Wsp + (size_t)(2 * w) * 65536;
    __half* lo = g_Wsp + (size_t)(2 * w + 1) * 65536;
    *reinterpret_cast<__half2*>(hi + o) = __halves2half2(h0, h1);
    *reinterpret_cast<__half2*>(lo + o) = __halves2half2(l0, l1);
}

__global__ void split_pair_kernel(const float* __restrict__ src,
                                  __half* __restrict__ hi, __half* __restrict__ lo,
                                  int n4) {
    int i = blockIdx.x * 256 + threadIdx.x;
    if (i < n4) {
        float4 v = reinterpret_cast<const float4*>(src)[i];
        __half h0, l0, h1, l1, h2, l2, h3, l3;
        h_split(v.x, h0, l0); h_split(v.y, h1, l1);
        h_split(v.z, h2, l2); h_split(v.w, h3, l3);
        reinterpret_cast<__half2*>(hi)[i * 2]     = __halves2half2(h0, h1);
        reinterpret_cast<__half2*>(hi)[i * 2 + 1] = __halves2half2(h2, h3);
        reinterpret_cast<__half2*>(lo)[i * 2]     = __halves2half2(l0, l1);
        reinterpret_cast<__half2*>(lo)[i * 2 + 1] = __halves2half2(l2, l3);
    }
}

__global__ void zero_agg_kernel(int n4) {
    int i = blockIdx.x * 256 + threadIdx.x;
    if (i < n4) reinterpret_cast<float4*>(g_agg)[i] = make_float4(0.f, 0.f, 0.f, 0.f);
}

__global__ void wr_kernel(const float* __restrict__ W1, const float* __restrict__ W2) {
    int c = threadIdx.x;
    #pragma unroll
    for (int k = 0; k < NRAD; k++) {
        float v = 0.f;
        #pragma unroll
        for (int j = 0; j < BAS; j++) v += W1[k * BAS + j] * W2[j * H + c];
        g_Wr[k * H + c] = v;
    }
}

__global__ void __launch_bounds__(256) rbfe_kernel(
    const float* __restrict__ rbf, float* __restrict__ out, int E) {
    __shared__ float srbf[64 * NRAD];
    const int tid = threadIdx.x;
    const int e0 = blockIdx.x * 64;
    float w[NRAD];
    #pragma unroll
    for (int k = 0; k < NRAD; k++) w[k] = g_Wr[k * H + tid];
    for (int i = tid; i < 64 * NRAD; i += 256) {
        int e = e0 + i / NRAD;
        srbf[i] = (e < E) ? rbf[(size_t)e * NRAD + (i % NRAD)] : 0.f;
    }
    __syncthreads();
    for (int r = 0; r < 64; r++) {
        int e = e0 + r;
        if (e >= E) break;
        float v = 0.f;
        #pragma unroll
        for (int k = 0; k < NRAD; k++) v += w[k] * srbf[r * NRAD + k];
        out[(size_t)e * H + tid] = v;
    }
}

// ---------------------------------------------------------------------------
// NEW: basis pre-transform  sb2[t,8] = sbf[t,:] @ W_sbf1
// ---------------------------------------------------------------------------
#define SBT 32
__global__ void __launch_bounds__(256) sbf_basis_kernel(
    const float* __restrict__ sbf, const float* __restrict__ W1, int T) {
    __shared__ float W1s[SBF_DIM * BAS];
    __shared__ float s[SBT][SBF_DIM];
    const int tid = threadIdx.x;
    for (int i = tid; i < SBF_DIM * BAS; i += 256) W1s[i] = W1[i];
    const long base = (long)blockIdx.x * SBT;
    for (int i = tid; i < SBT * SBF_DIM; i += 256) {
        long t = base + i / SBF_DIM;
        s[i / SBF_DIM][i % SBF_DIM] = (t < T) ? sbf[t * SBF_DIM + i % SBF_DIM] : 0.f;
    }
    __syncthreads();
    const int t = tid >> 3, j = tid & 7;
    const long tri = base + t;
    if (tri < T) {
        float v = 0.f;
        #pragma unroll
        for (int k = 0; k < SBF_DIM; k++) v += s[t][k] * W1s[k * BAS + j];
        g_sb2[tri * BAS + j] = v;
    }
}

// ---------------------------------------------------------------------------
// NEW: barrier-free scatter: 16 lanes/triplet, W2 in registers
// ---------------------------------------------------------------------------
#define S2_ITER 8
__global__ void __launch_bounds__(512) scatter2_kernel(
    const int* __restrict__ idx_kj, const int* __restrict__ idx_ji,
    const float* __restrict__ W2, int T) {
    const int tid = threadIdx.x;
    const int c0 = (tid & 15) * 4;
    float4 w2[BAS];
    #pragma unroll
    for (int k = 0; k < BAS; k++)
        w2[k] = __ldg(reinterpret_cast<const float4*>(&W2[k * INTC + c0]));

    const int grp = tid >> 4;   // 0..31
    const long tri0 = (long)blockIdx.x * (32 * S2_ITER) + grp;
    #pragma unroll
    for (int i = 0; i < S2_ITER; i++) {
        const long tri = tri0 + (long)i * 32;
        if (tri >= (long)T) break;
        const float4 b0 = __ldg(reinterpret_cast<const float4*>(&g_sb2[tri * BAS]));
        const float4 b1 = __ldg(reinterpret_cast<const float4*>(&g_sb2[tri * BAS + 4]));
        const int kj = __ldg(&idx_kj[tri]);
        const int ji = __ldg(&idx_ji[tri]);
        const float bb[BAS] = {b0.x, b0.y, b0.z, b0.w, b1.x, b1.y, b1.z, b1.w};
        float s0 = 0.f, s1 = 0.f, s2 = 0.f, s3 = 0.f;
        #pragma unroll
        for (int k = 0; k < BAS; k++) {
            s0 += bb[k] * w2[k].x; s1 += bb[k] * w2[k].y;
            s2 += bb[k] * w2[k].z; s3 += bb[k] * w2[k].w;
        }
        const float4 d = __ldg(reinterpret_cast<const float4*>(&g_down[(size_t)kj * INTC + c0]));
        s0 *= d.x; s1 *= d.y; s2 *= d.z; s3 *= d.w;
        float* dst = &g_agg[(size_t)ji * INTC + c0];
        asm volatile("red.global.add.v4.f32 [%0], {%1,%2,%3,%4};"
                     :: "l"(dst), "f"(s0), "f"(s1), "f"(s2), "f"(s3) : "memory");
    }
}

// ---------------------------------------------------------------------------
// Host orchestration
// ---------------------------------------------------------------------------
struct Pair { __half* h; __half* l; };

#define SMEM_BIG  (4 * (12288 + 2 * 4096))
#define SMEM_SML  (4 * (12288 + 2 * 2048))

static inline void launch_gemm(Pair A, const __half* bh, const __half* bl,
                               const float* bias, const float* mul, const float* addF,
                               Pair addP, float* Cf, Pair Cp,
                               int M, int N, int K, int ncblk) {
    if (K == 256 && N == 256) {
        dim3 grid((M + BM - 1) / BM, 2);
        gemm_f16x2<16, 8, 4><<<grid, 256, SMEM_BIG>>>(A.h, A.l, bh, bl, bias, mul, addF,
                                                      addP.h, addP.l, Cf, Cp.h, Cp.l, M, N);
    } else if (K == 256) {
        dim3 grid((M + BM - 1) / BM, 1);
        gemm_f16x2<16, 4, 2><<<grid, 256, SMEM_SML>>>(A.h, A.l, bh, bl, bias, mul, addF,
                                                      addP.h, addP.l, Cf, Cp.h, Cp.l, M, N);
    } else {
        dim3 grid((M + BM - 1) / BM, 2);
        gemm_f16x2<4, 8, 4><<<grid, 256, SMEM_BIG>>>(A.h, A.l, bh, bl, bias, mul, addF,
                                                     addP.h, addP.l, Cf, Cp.h, Cp.l, M, N);
    }
}

extern "C" void kernel_launch(void* const* d_in, const int* in_sizes, int n_in,
                              void* d_out, int out_size) {
    const float* x      = (const float*)d_in[0];
    const float* rbf    = (const float*)d_in[1];
    const float* sbf    = (const float*)d_in[2];
    const int*   idx_kj = (const int*)d_in[3];
    const int*   idx_ji = (const int*)d_in[4];
    const float* W_rbf1 = (const float*)d_in[5];
    const float* W_rbf2 = (const float*)d_in[6];
    const float* W_sbf1 = (const float*)d_in[7];
    const float* W_sbf2 = (const float*)d_in[8];
    const float* W_kj   = (const float*)d_in[9];
    const float* b_kj   = (const float*)d_in[10];
    const float* W_ji   = (const float*)d_in[11];
    const float* b_ji   = (const float*)d_in[12];
    const float* W_down = (const float*)d_in[13];
    const float* W_up   = (const float*)d_in[14];
    const float* rb_W1  = (const float*)d_in[15];
    const float* rb_b1  = (const float*)d_in[16];
    const float* rb_W2  = (const float*)d_in[17];
    const float* rb_b2  = (const float*)d_in[18];
    const float* W_lin  = (const float*)d_in[19];
    const float* b_lin  = (const float*)d_in[20];
    const float* ra_W1  = (const float*)d_in[21];
    const float* ra_b1  = (const float*)d_in[22];
    const float* ra_W2  = (const float*)d_in[23];
    const float* ra_b2  = (const float*)d_in[24];

    const int E = in_sizes[0] / H;
    const int T = in_sizes[3];
    float* out = (float*)d_out;

    cudaFuncSetAttribute((const void*)gemm_f16x2<16, 8, 4>,
                         cudaFuncAttributeMaxDynamicSharedMemorySize, SMEM_BIG);
    cudaFuncSetAttribute((const void*)gemm_f16x2<16, 4, 2>,
                         cudaFuncAttributeMaxDynamicSharedMemorySize, SMEM_SML);
    cudaFuncSetAttribute((const void*)gemm_f16x2<4, 8, 4>,
                         cudaFuncAttributeMaxDynamicSharedMemorySize, SMEM_BIG);

    float *buf0, *buf1, *down, *agg;
    __half *P0h, *P0l, *P1h, *P1l, *P2h, *P2l, *aggh, *aggl, *wsp;
    cudaGetSymbolAddress((void**)&buf0, g_buf0);
    cudaGetSymbolAddress((void**)&buf1, g_buf1);
    cudaGetSymbolAddress((void**)&down, g_down);
    cudaGetSymbolAddress((void**)&agg,  g_agg);
    cudaGetSymbolAddress((void**)&P0h, g_P0h); cudaGetSymbolAddress((void**)&P0l, g_P0l);
    cudaGetSymbolAddress((void**)&P1h, g_P1h); cudaGetSymbolAddress((void**)&P1l, g_P1l);
    cudaGetSymbolAddress((void**)&P2h, g_P2h); cudaGetSymbolAddress((void**)&P2l, g_P2l);
    cudaGetSymbolAddress((void**)&aggh, g_aggh); cudaGetSymbolAddress((void**)&aggl, g_aggl);
    cudaGetSymbolAddress((void**)&wsp, g_Wsp);
    #define WHI(w) (wsp + (size_t)(2 * (w)) * 65536)
    #define WLO(w) (wsp + (size_t)(2 * (w) + 1) * 65536)

    const Pair P0{P0h, P0l}, P1{P1h, P1l}, P2{P2h, P2l}, Pagg{aggh, aggl};
    const Pair NOP{nullptr, nullptr};

    split_w_kernel<<<dim3(128, 11), 256>>>(
        W_ji, W_kj, W_down, W_up, rb_W1, rb_W2, W_lin, ra_W1, ra_W2,
        ra_W1 + (size_t)H * H, ra_W2 + (size_t)H * H);
    wr_kernel<<<1, 256>>>(W_rbf1, W_rbf2);
    split_pair_kernel<<<((E * H / 4) + 255) / 256, 256>>>(x, P0h, P0l, E * H / 4);

    // big GEMM (ncu slot position preserved)
    launch_gemm(P0, WHI(0), WLO(0), b_ji, nullptr, nullptr, NOP, buf0, NOP, E, H, H, 8);

    sbf_basis_kernel<<<(T + SBT - 1) / SBT, 256>>>(sbf, W_sbf1, T);
    rbfe_kernel<<<(E + 63) / 64, 256>>>(rbf, buf1, E);
    zero_agg_kernel<<<(E * INTC / 4 + 255) / 256, 256>>>(E * INTC / 4);
    launch_gemm(P0, WHI(1), WLO(1), b_kj, buf1, nullptr, NOP, nullptr, P1, E, H, H, 8);
    launch_gemm(P1, WHI(2), WLO(2), nullptr, nullptr, nullptr, NOP, down, NOP, E, INTC, H, 4);

    scatter2_kernel<<<(T + 32 * S2_ITER - 1) / (32 * S2_ITER), 512>>>(idx_kj, idx_ji, W_sbf2, T);
    split_pair_kernel<<<((E * INTC / 4) + 255) / 256, 256>>>(agg, aggh, aggl, E * INTC / 4);

    launch_gemm(Pagg, WHI(3), WLO(3), nullptr, nullptr, buf0, NOP, nullptr, P2, E, H, INTC, 8);
    launch_gemm(P2, WHI(4), WLO(4), rb_b1, nullptr, nullptr, NOP, nullptr, P1, E, H, H, 8);
    launch_gemm(P1, WHI(5), WLO(5), rb_b2, nullptr, nullptr, P2, nullptr, P0, E, H, H, 8);
    launch_gemm(P0, WHI(6), WLO(6), b_lin, nullptr, x, NOP, nullptr, P2, E, H, H, 8);
    launch_gemm(P2, WHI(7), WLO(7), ra_b1, nullptr, nullptr, NOP, nullptr, P1, E, H, H, 8);
    launch_gemm(P1, WHI(8), WLO(8), ra_b2, nullptr, nullptr, P2, nullptr, P0, E, H, H, 8);
    launch_gemm(P0, WHI(9), WLO(9), ra_b1 + H, nullptr, nullptr, NOP, nullptr, P1, E, H, H, 8);
    launch_gemm(P1, WHI(10), WLO(10), ra_b2 + H, nullptr, nullptr, P0, out, NOP, E, H, H, 8);
}

// round 12
// speedup vs baseline: 1.0687x; 1.0687x over previous
#include <cuda_runtime.h>
#include <cuda_fp16.h>
#include <cstdint>

// ---------------------------------------------------------------------------
// InteractionPPBlock (DimeNet++) — round 12: stream-forked graph (scatter
// overlaps x_ji GEMM), rbf_e fused into x_kj GEMM epilogue
// ---------------------------------------------------------------------------

#define H 256
#define INTC 64
#define SBF_DIM 42
#define NRAD 6
#define BAS 8

#define MAXE 200704
#define MAXT 2000000
#define MAXE_H ((size_t)MAXE * H)
#define MAXE_I ((size_t)MAXE * INTC)

__device__ float g_buf0[MAXE_H];
__device__ float g_down[MAXE_I];
__device__ float g_agg[MAXE_I];
__device__ float g_Wr[NRAD * H];
__device__ float g_sb2[(size_t)MAXT * BAS];
__device__ __half g_P0h[MAXE_H], g_P0l[MAXE_H];
__device__ __half g_P1h[MAXE_H], g_P1l[MAXE_H];
__device__ __half g_P2h[MAXE_H], g_P2l[MAXE_H];
__device__ __half g_aggh[MAXE_I], g_aggl[MAXE_I];
__device__ __half g_Wsp[22 * 65536];

__device__ __forceinline__ float silu(float v) {
    return v / (1.0f + __expf(-v));
}
__device__ __forceinline__ void h_split(float v, __half& h, __half& l) {
    h = __float2half_rn(v);
    l = __float2half_rn(v - __half2float(h));
}

__device__ __forceinline__ void mma_f16(float* d, const uint32_t* a, const uint32_t* b) {
    asm volatile(
        "mma.sync.aligned.m16n8k16.row.col.f32.f16.f16.f32 "
        "{%0,%1,%2,%3},{%4,%5,%6,%7},{%8,%9},{%0,%1,%2,%3};\n"
        : "+f"(d[0]), "+f"(d[1]), "+f"(d[2]), "+f"(d[3])
        : "r"(a[0]), "r"(a[1]), "r"(a[2]), "r"(a[3]), "r"(b[0]), "r"(b[1]));
}
__device__ __forceinline__ void ldsm_x4(uint32_t* r, uint32_t addr) {
    asm volatile("ldmatrix.sync.aligned.m8n8.x4.shared.b16 {%0,%1,%2,%3}, [%4];"
                 : "=r"(r[0]), "=r"(r[1]), "=r"(r[2]), "=r"(r[3]) : "r"(addr));
}

__device__ __forceinline__ uint32_t smem_u32(const void* p) {
    uint32_t a;
    asm("{ .reg .u64 t; cvta.to.shared.u64 t, %1; cvt.u32.u64 %0, t; }" : "=r"(a) : "l"(p));
    return a;
}
__device__ __forceinline__ void cp_async16(uint32_t dst, const void* src, int szr) {
    asm volatile("cp.async.cg.shared.global [%0], [%1], 16, %2;"
                 :: "r"(dst), "l"(src), "r"(szr) : "memory");
}
#define CP_COMMIT() asm volatile("cp.async.commit_group;" ::: "memory")
#define CP_WAIT(n)  asm volatile("cp.async.wait_group %0;" :: "n"(n) : "memory")

// ---------------------------------------------------------------------------
// GEMM: BM=128, BN=32*NBLK, BK=16, 256 thr, 4 stages (mainloop = R10/R11)
// epilogue: (+bias) -> silu -> (*rbf_e on the fly | *mul) -> (+add) -> out
// ---------------------------------------------------------------------------
#define BM 128
#define STAGES 4

template <int NK, int NCBLK, int NBLK>
__global__ void __launch_bounds__(256, 2) gemm_f16x2(
    const __half* __restrict__ Ah, const __half* __restrict__ Al,
    const __half* __restrict__ Bh, const __half* __restrict__ Bl,
    const float* __restrict__ bias, const float* __restrict__ rbf6,
    const float* __restrict__ addF,
    const __half* __restrict__ addH, const __half* __restrict__ addL,
    float* __restrict__ Cf, __half* __restrict__ Chi, __half* __restrict__ Clo,
    int M, int N) {

    constexpr int NT   = NBLK * 2;
    constexpr int BSTG = NBLK * 1024;
    constexpr int STG  = 12288 + 2 * BSTG;
    constexpr int BN   = NBLK * 32;
    constexpr int K    = NK * 16;

    extern __shared__ char smem_raw[];
    char* bp = smem_raw;
    const uint32_t s0 = smem_u32(smem_raw);

    const int tid  = threadIdx.x;
    const int wid  = tid >> 5;
    const int lane = tid & 31;
    const int g    = lane >> 2;
    const int t    = lane & 3;
    const int wy   = wid >> 1;
    const int wx   = wid & 1;

    const int rowBase = blockIdx.x * BM;
    const int colBase = blockIdx.y * BN;
    const int cblk0   = colBase >> 5;

    const int ar = tid >> 1, ac = tid & 1;
    const int gr = rowBase + ar;
    const bool aV = gr < M;
    const __half* aSrcH = Ah + (size_t)(aV ? gr : 0) * K + ac * 8;
    const __half* aSrcL = Al + (size_t)(aV ? gr : 0) * K + ac * 8;
    const uint32_t aDstH = s0 + (uint32_t)(ar * 48 + ac * 16);
    const uint32_t aDstL = aDstH + 6144u;
    constexpr int bStep = NCBLK * 512;

    int bChunk;
    const __half* bSrc0;
    const __half* bSrc1;
    uint32_t bDst0, bDst1;
    if (NBLK == 4) {
        bChunk = tid;
        const int cblkL = bChunk >> 6, rr = (bChunk >> 5) & 1, bln = bChunk & 31;
        const size_t off = ((size_t)((cblk0 + cblkL) * 2 + rr) * 32 + bln) * 8;
        bSrc0 = Bh + off;
        bSrc1 = Bl + off;
        bDst0 = s0 + 12288u + (uint32_t)bChunk * 16;
        bDst1 = bDst0 + (uint32_t)BSTG;
    } else {
        bChunk = tid & 127;
        const int cblkL = bChunk >> 6, rr = (bChunk >> 5) & 1, bln = bChunk & 31;
        const size_t off = ((size_t)((cblk0 + cblkL) * 2 + rr) * 32 + bln) * 8;
        bSrc0 = ((tid < 128) ? Bh : Bl) + off;
        bSrc1 = nullptr;
        bDst0 = s0 + 12288u + (tid < 128 ? 0u : (uint32_t)BSTG) + (uint32_t)bChunk * 16;
        bDst1 = 0;
    }

    const uint32_t lds_a_off =
        (uint32_t)(((lane & 7) + ((lane >> 3) & 1) * 8) * 48 + ((lane >> 4) & 1) * 16);

    float acc[2][NT][4];
    #pragma unroll
    for (int i = 0; i < 2; i++)
        #pragma unroll
        for (int j = 0; j < NT; j++)
            #pragma unroll
            for (int r = 0; r < 4; r++) acc[i][j][r] = 0.f;

    #pragma unroll
    for (int s = 0; s < STAGES - 1; s++) {
        if (s < NK) {
            cp_async16(aDstH + s * STG, aSrcH + s * 16, aV ? 16 : 0);
            cp_async16(aDstL + s * STG, aSrcL + s * 16, aV ? 16 : 0);
            cp_async16(bDst0 + s * STG, bSrc0 + (size_t)s * bStep, 16);
            if (NBLK == 4)
                cp_async16(bDst1 + s * STG, bSrc1 + (size_t)s * bStep, 16);
        }
        CP_COMMIT();
    }

    #pragma unroll
    for (int it = 0; it < NK; ++it) {
        const int pend = NK - 1 - it;
        if (pend >= 2)      CP_WAIT(2);
        else if (pend == 1) CP_WAIT(1);
        else                CP_WAIT(0);
        __syncthreads();

        const int nx = it + STAGES - 1;
        if (nx < NK) {
            const uint32_t so = (uint32_t)(nx % STAGES) * STG;
            cp_async16(aDstH + so, aSrcH + nx * 16, aV ? 16 : 0);
            cp_async16(aDstL + so, aSrcL + nx * 16, aV ? 16 : 0);
            cp_async16(bDst0 + so, bSrc0 + (size_t)nx * bStep, 16);
            if (NBLK == 4)
                cp_async16(bDst1 + so, bSrc1 + (size_t)nx * bStep, 16);
            CP_COMMIT();
        }

        const uint32_t sb = (uint32_t)(it % STAGES) * STG;
        const uint32_t bHiBase = sb + 12288u;
        const uint32_t bLoBase = bHiBase + (uint32_t)BSTG;

        uint32_t ah[2][4], al[2][4];
        #pragma unroll
        for (int mt = 0; mt < 2; mt++) {
            const int m0 = wy * 32 + mt * 16;
            ldsm_x4(ah[mt], s0 + sb + (uint32_t)(m0 * 48) + lds_a_off);
            ldsm_x4(al[mt], s0 + sb + 6144u + (uint32_t)(m0 * 48) + lds_a_off);
        }

        uint32_t bh[NT][2];
        #pragma unroll
        for (int j = 0; j < NBLK / 2; j++) {
            const int cb = wx * (NBLK / 2) + j;
            uint4 v0 = *reinterpret_cast<uint4*>(bp + bHiBase + ((cb * 2 + 0) * 32 + lane) * 16);
            uint4 v1 = *reinterpret_cast<uint4*>(bp + bHiBase + ((cb * 2 + 1) * 32 + lane) * 16);
            bh[j * 4 + 0][0] = v0.x; bh[j * 4 + 1][0] = v0.y;
            bh[j * 4 + 2][0] = v0.z; bh[j * 4 + 3][0] = v0.w;
            bh[j * 4 + 0][1] = v1.x; bh[j * 4 + 1][1] = v1.y;
            bh[j * 4 + 2][1] = v1.z; bh[j * 4 + 3][1] = v1.w;
        }

        #pragma unroll
        for (int mt = 0; mt < 2; mt++)
            #pragma unroll
            for (int nt = 0; nt < NT; nt++)
                mma_f16(acc[mt][nt], al[mt], bh[nt]);

        uint32_t bl[NT][2];
        #pragma unroll
        for (int j = 0; j < NBLK / 2; j++) {
            const int cb = wx * (NBLK / 2) + j;
            uint4 v0 = *reinterpret_cast<uint4*>(bp + bLoBase + ((cb * 2 + 0) * 32 + lane) * 16);
            uint4 v1 = *reinterpret_cast<uint4*>(bp + bLoBase + ((cb * 2 + 1) * 32 + lane) * 16);
            bl[j * 4 + 0][0] = v0.x; bl[j * 4 + 1][0] = v0.y;
            bl[j * 4 + 2][0] = v0.z; bl[j * 4 + 3][0] = v0.w;
            bl[j * 4 + 0][1] = v1.x; bl[j * 4 + 1][1] = v1.y;
            bl[j * 4 + 2][1] = v1.z; bl[j * 4 + 3][1] = v1.w;
        }

        #pragma unroll
        for (int mt = 0; mt < 2; mt++)
            #pragma unroll
            for (int nt = 0; nt < NT; nt++)
                mma_f16(acc[mt][nt], ah[mt], bl[nt]);

        #pragma unroll
        for (int mt = 0; mt < 2; mt++)
            #pragma unroll
            for (int nt = 0; nt < NT; nt++)
                mma_f16(acc[mt][nt], ah[mt], bh[nt]);
    }

    // ---- epilogue (row-major loop so rbf row loads amortize) ----
    #pragma unroll
    for (int mt = 0; mt < 2; mt++) {
        #pragma unroll
        for (int half = 0; half < 2; half++) {
            const int row = rowBase + wy * 32 + mt * 16 + g + 8 * half;
            if (row >= M) continue;
            float r6[NRAD];
            if (rbf6) {
                #pragma unroll
                for (int k = 0; k < NRAD; k++) r6[k] = rbf6[(size_t)row * NRAD + k];
            }
            #pragma unroll
            for (int nt = 0; nt < NT; nt++) {
                const int c0 = colBase + wx * (NT * 8) + nt * 8 + 2 * t;
                if (c0 >= N) continue;
                const size_t idx = (size_t)row * N + c0;
                float v0 = acc[mt][nt][half * 2];
                float v1 = acc[mt][nt][half * 2 + 1];
                if (bias) { v0 += bias[c0]; v1 += bias[c0 + 1]; }
                v0 = silu(v0); v1 = silu(v1);
                if (rbf6) {
                    float m0 = 0.f, m1 = 0.f;
                    #pragma unroll
                    for (int k = 0; k < NRAD; k++) {
                        m0 += r6[k] * g_Wr[k * H + c0];
                        m1 += r6[k] * g_Wr[k * H + c0 + 1];
                    }
                    v0 *= m0; v1 *= m1;
                }
                if (addF) { v0 += addF[idx]; v1 += addF[idx + 1]; }
                if (addH) {
                    v0 += __half2float(addH[idx]) + __half2float(addL[idx]);
                    v1 += __half2float(addH[idx + 1]) + __half2float(addL[idx + 1]);
                }
                if (Cf) { Cf[idx] = v0; Cf[idx + 1] = v1; }
                if (Chi) {
                    __half h0, l0, h1, l1;
                    h_split(v0, h0, l0); h_split(v1, h1, l1);
                    *reinterpret_cast<__half2*>(Chi + idx) = __halves2half2(h0, h1);
                    *reinterpret_cast<__half2*>(Clo + idx) = __halves2half2(l0, l1);
                }
            }
        }
    }
}

// ---------------------------------------------------------------------------
// Prep kernels
// ---------------------------------------------------------------------------
__global__ void split_w_kernel(
    const float* p0, const float* p1, const float* p2, const float* p3,
    const float* p4, const float* p5, const float* p6, const float* p7,
    const float* p8, const float* p9, const float* p10) {
    const float* srcs[11] = {p0, p1, p2, p3, p4, p5, p6, p7, p8, p9, p10};
    const int KK[11]  = {256, 256, 256, 64, 256, 256, 256, 256, 256, 256, 256};
    const int NN[11]  = {256, 256, 64, 256, 256, 256, 256, 256, 256, 256, 256};
    const int NC[11]  = {8, 8, 4, 8, 8, 8, 8, 8, 8, 8, 8};
    const int w = blockIdx.y;
    const int i = blockIdx.x * 256 + threadIdx.x;
    const int K = KK[w], N = NN[w], ncblk = NC[w];
    const int total = (K / 16) * ncblk * 256;
    if (i >= total) return;
    const int kb = i / (ncblk * 256);
    const int rem = i % (ncblk * 256);
    const int cblk = rem >> 8;
    const int j = rem & 255;
    const int r = j >> 7, lane = (j >> 2) & 31, nt = j & 3;
    const int gg = lane >> 2, tt = lane & 3;
    const int k0 = kb * 16 + r * 8 + tt * 2;
    const int n  = cblk * 32 + nt * 8 + gg;
    const float* W = srcs[w];
    float v0 = (n < N && k0 < K)     ? W[(size_t)k0 * N + n]       : 0.f;
    float v1 = (n < N && k0 + 1 < K) ? W[(size_t)(k0 + 1) * N + n] : 0.f;
    __half h0, l0, h1, l1;
    h_split(v0, h0, l0); h_split(v1, h1, l1);
    const size_t o = (size_t)i * 2;
    __half* hi = g_Wsp + (size_t)(2 * w) * 65536;
    __half* lo = g_Wsp + (size_t)(2 * w + 1) * 65536;
    *reinterpret_cast<__half2*>(hi + o) = __halves2half2(h0, h1);
    *reinterpret_cast<__half2*>(lo + o) = __halves2half2(l0, l1);
}

__global__ void split_pair_kernel(const float* __restrict__ src,
                                  __half* __restrict__ hi, __half* __restrict__ lo,
                                  int n4) {
    int i = blockIdx.x * 256 + threadIdx.x;
    if (i < n4) {
        float4 v = reinterpret_cast<const float4*>(src)[i];
        __half h0, l0, h1, l1, h2, l2, h3, l3;
        h_split(v.x, h0, l0); h_split(v.y, h1, l1);
        h_split(v.z, h2, l2); h_split(v.w, h3, l3);
        reinterpret_cast<__half2*>(hi)[i * 2]     = __halves2half2(h0, h1);
        reinterpret_cast<__half2*>(hi)[i * 2 + 1] = __halves2half2(h2, h3);
        reinterpret_cast<__half2*>(lo)[i * 2]     = __halves2half2(l0, l1);
        reinterpret_cast<__half2*>(lo)[i * 2 + 1] = __halves2half2(l2, l3);
    }
}

__global__ void zero_agg_kernel(int n4) {
    int i = blockIdx.x * 256 + threadIdx.x;
    if (i < n4) reinterpret_cast<float4*>(g_agg)[i] = make_float4(0.f, 0.f, 0.f, 0.f);
}

__global__ void wr_kernel(const float* __restrict__ W1, const float* __restrict__ W2) {
    int c = threadIdx.x;
    #pragma unroll
    for (int k = 0; k < NRAD; k++) {
        float v = 0.f;
        #pragma unroll
        for (int j = 0; j < BAS; j++) v += W1[k * BAS + j] * W2[j * H + c];
        g_Wr[k * H + c] = v;
    }
}

// basis pre-transform  sb2[t,8] = sbf[t,:] @ W_sbf1
#define SBT 32
__global__ void __launch_bounds__(256) sbf_basis_kernel(
    const float* __restrict__ sbf, const float* __restrict__ W1, int T) {
    __shared__ float W1s[SBF_DIM * BAS];
    __shared__ float s[SBT][SBF_DIM];
    const int tid = threadIdx.x;
    for (int i = tid; i < SBF_DIM * BAS; i += 256) W1s[i] = W1[i];
    const long base = (long)blockIdx.x * SBT;
    for (int i = tid; i < SBT * SBF_DIM; i += 256) {
        long t = base + i / SBF_DIM;
        s[i / SBF_DIM][i % SBF_DIM] = (t < T) ? sbf[t * SBF_DIM + i % SBF_DIM] : 0.f;
    }
    __syncthreads();
    const int t = tid >> 3, j = tid & 7;
    const long tri = base + t;
    if (tri < T) {
        float v = 0.f;
        #pragma unroll
        for (int k = 0; k < SBF_DIM; k++) v += s[t][k] * W1s[k * BAS + j];
        g_sb2[tri * BAS + j] = v;
    }
}

// barrier-free scatter: 16 lanes/triplet, W2 in registers
#define S2_ITER 8
__global__ void __launch_bounds__(512) scatter2_kernel(
    const int* __restrict__ idx_kj, const int* __restrict__ idx_ji,
    const float* __restrict__ W2, int T) {
    const int tid = threadIdx.x;
    const int c0 = (tid & 15) * 4;
    float4 w2[BAS];
    #pragma unroll
    for (int k = 0; k < BAS; k++)
        w2[k] = __ldg(reinterpret_cast<const float4*>(&W2[k * INTC + c0]));

    const int grp = tid >> 4;
    const long tri0 = (long)blockIdx.x * (32 * S2_ITER) + grp;
    #pragma unroll
    for (int i = 0; i < S2_ITER; i++) {
        const long tri = tri0 + (long)i * 32;
        if (tri >= (long)T) break;
        const float4 b0 = __ldg(reinterpret_cast<const float4*>(&g_sb2[tri * BAS]));
        const float4 b1 = __ldg(reinterpret_cast<const float4*>(&g_sb2[tri * BAS + 4]));
        const int kj = __ldg(&idx_kj[tri]);
        const int ji = __ldg(&idx_ji[tri]);
        const float bb[BAS] = {b0.x, b0.y, b0.z, b0.w, b1.x, b1.y, b1.z, b1.w};
        float s0 = 0.f, s1 = 0.f, s2 = 0.f, s3 = 0.f;
        #pragma unroll
        for (int k = 0; k < BAS; k++) {
            s0 += bb[k] * w2[k].x; s1 += bb[k] * w2[k].y;
            s2 += bb[k] * w2[k].z; s3 += bb[k] * w2[k].w;
        }
        const float4 d = __ldg(reinterpret_cast<const float4*>(&g_down[(size_t)kj * INTC + c0]));
        s0 *= d.x; s1 *= d.y; s2 *= d.z; s3 *= d.w;
        float* dst = &g_agg[(size_t)ji * INTC + c0];
        asm volatile("red.global.add.v4.f32 [%0], {%1,%2,%3,%4};"
                     :: "l"(dst), "f"(s0), "f"(s1), "f"(s2), "f"(s3) : "memory");
    }
}

// ---------------------------------------------------------------------------
// Host orchestration
// ---------------------------------------------------------------------------
struct Pair { __half* h; __half* l; };

#define SMEM_BIG  (4 * (12288 + 2 * 4096))
#define SMEM_SML  (4 * (12288 + 2 * 2048))

static inline void launch_gemm(cudaStream_t st, Pair A, const __half* bh, const __half* bl,
                               const float* bias, const float* rbf6, const float* addF,
                               Pair addP, float* Cf, Pair Cp,
                               int M, int N, int K) {
    if (K == 256 && N == 256) {
        dim3 grid((M + BM - 1) / BM, 2);
        gemm_f16x2<16, 8, 4><<<grid, 256, SMEM_BIG, st>>>(A.h, A.l, bh, bl, bias, rbf6, addF,
                                                          addP.h, addP.l, Cf, Cp.h, Cp.l, M, N);
    } else if (K == 256) {
        dim3 grid((M + BM - 1) / BM, 1);
        gemm_f16x2<16, 4, 2><<<grid, 256, SMEM_SML, st>>>(A.h, A.l, bh, bl, bias, rbf6, addF,
                                                          addP.h, addP.l, Cf, Cp.h, Cp.l, M, N);
    } else {
        dim3 grid((M + BM - 1) / BM, 2);
        gemm_f16x2<4, 8, 4><<<grid, 256, SMEM_BIG, st>>>(A.h, A.l, bh, bl, bias, rbf6, addF,
                                                         addP.h, addP.l, Cf, Cp.h, Cp.l, M, N);
    }
}

extern "C" void kernel_launch(void* const* d_in, const int* in_sizes, int n_in,
                              void* d_out, int out_size) {
    const float* x      = (const float*)d_in[0];
    const float* rbf    = (const float*)d_in[1];
    const float* sbf    = (const float*)d_in[2];
    const int*   idx_kj = (const int*)d_in[3];
    const int*   idx_ji = (const int*)d_in[4];
    const float* W_rbf1 = (const float*)d_in[5];
    const float* W_rbf2 = (const float*)d_in[6];
    const float* W_sbf1 = (const float*)d_in[7];
    const float* W_sbf2 = (const float*)d_in[8];
    const float* W_kj   = (const float*)d_in[9];
    const float* b_kj   = (const float*)d_in[10];
    const float* W_ji   = (const float*)d_in[11];
    const float* b_ji   = (const float*)d_in[12];
    const float* W_down = (const float*)d_in[13];
    const float* W_up   = (const float*)d_in[14];
    const float* rb_W1  = (const float*)d_in[15];
    const float* rb_b1  = (const float*)d_in[16];
    const float* rb_W2  = (const float*)d_in[17];
    const float* rb_b2  = (const float*)d_in[18];
    const float* W_lin  = (const float*)d_in[19];
    const float* b_lin  = (const float*)d_in[20];
    const float* ra_W1  = (const float*)d_in[21];
    const float* ra_b1  = (const float*)d_in[22];
    const float* ra_W2  = (const float*)d_in[23];
    const float* ra_b2  = (const float*)d_in[24];

    const int E = in_sizes[0] / H;
    const int T = in_sizes[3];
    float* out = (float*)d_out;

    // lazily-created side stream + fork/join events (host objects only)
    static cudaStream_t s2 = nullptr;
    static cudaEvent_t eA = nullptr, eB = nullptr, eC = nullptr;
    if (!s2) {
        cudaStreamCreateWithFlags(&s2, cudaStreamNonBlocking);
        cudaEventCreateWithFlags(&eA, cudaEventDisableTiming);
        cudaEventCreateWithFlags(&eB, cudaEventDisableTiming);
        cudaEventCreateWithFlags(&eC, cudaEventDisableTiming);
    }

    cudaFuncSetAttribute((const void*)gemm_f16x2<16, 8, 4>,
                         cudaFuncAttributeMaxDynamicSharedMemorySize, SMEM_BIG);
    cudaFuncSetAttribute((const void*)gemm_f16x2<16, 4, 2>,
                         cudaFuncAttributeMaxDynamicSharedMemorySize, SMEM_SML);
    cudaFuncSetAttribute((const void*)gemm_f16x2<4, 8, 4>,
                         cudaFuncAttributeMaxDynamicSharedMemorySize, SMEM_BIG);

    float *buf0, *down, *agg;
    __half *P0h, *P0l, *P1h, *P1l, *P2h, *P2l, *aggh, *aggl, *wsp;
    cudaGetSymbolAddress((void**)&buf0, g_buf0);
    cudaGetSymbolAddress((void**)&down, g_down);
    cudaGetSymbolAddress((void**)&agg,  g_agg);
    cudaGetSymbolAddress((void**)&P0h, g_P0h); cudaGetSymbolAddress((void**)&P0l, g_P0l);
    cudaGetSymbolAddress((void**)&P1h, g_P1h); cudaGetSymbolAddress((void**)&P1l, g_P1l);
    cudaGetSymbolAddress((void**)&P2h, g_P2h); cudaGetSymbolAddress((void**)&P2l, g_P2l);
    cudaGetSymbolAddress((void**)&aggh, g_aggh); cudaGetSymbolAddress((void**)&aggl, g_aggl);
    cudaGetSymbolAddress((void**)&wsp, g_Wsp);
    #define WHI(w) (wsp + (size_t)(2 * (w)) * 65536)
    #define WLO(w) (wsp + (size_t)(2 * (w) + 1) * 65536)

    const Pair P0{P0h, P0l}, P1{P1h, P1l}, P2{P2h, P2l}, Pagg{aggh, aggl};
    const Pair NOP{nullptr, nullptr};
    cudaStream_t D = 0;   // legacy default (matches <<<>>> semantics + harness capture)

    // ---- prologue on D ----
    split_w_kernel<<<dim3(128, 11), 256, 0, D>>>(
        W_ji, W_kj, W_down, W_up, rb_W1, rb_W2, W_lin, ra_W1, ra_W2,
        ra_W1 + (size_t)H * H, ra_W2 + (size_t)H * H);
    wr_kernel<<<1, 256, 0, D>>>(W_rbf1, W_rbf2);
    split_pair_kernel<<<((E * H / 4) + 255) / 256, 256, 0, D>>>(x, P0h, P0l, E * H / 4);
    zero_agg_kernel<<<(E * INTC / 4 + 255) / 256, 256, 0, D>>>(E * INTC / 4);
    cudaEventRecord(eA, D);

    // ---- branch S: basis transform (parallel with x_kj GEMM) ----
    cudaStreamWaitEvent(s2, eA, 0);
    sbf_basis_kernel<<<(T + SBT - 1) / SBT, 256, 0, s2>>>(sbf, W_sbf1, T);

    // ---- D: x_kj (rbf_e fused in epilogue) + down projection ----
    launch_gemm(D, P0, WHI(1), WLO(1), b_kj, rbf, nullptr, NOP, nullptr, P1, E, H, H);
    launch_gemm(D, P1, WHI(2), WLO(2), nullptr, nullptr, nullptr, NOP, down, NOP, E, INTC, H);
    cudaEventRecord(eB, D);

    // ---- branch S: scatter + agg split (needs sb2 + down) ----
    cudaStreamWaitEvent(s2, eB, 0);
    scatter2_kernel<<<(T + 32 * S2_ITER - 1) / (32 * S2_ITER), 512, 0, s2>>>(idx_kj, idx_ji, W_sbf2, T);
    split_pair_kernel<<<((E * INTC / 4) + 255) / 256, 256, 0, s2>>>(agg, aggh, aggl, E * INTC / 4);
    cudaEventRecord(eC, s2);

    // ---- D: x_ji GEMM runs concurrently with scatter branch ----
    launch_gemm(D, P0, WHI(0), WLO(0), b_ji, nullptr, nullptr, NOP, buf0, NOP, E, H, H);

    // ---- join, then serial chain on D ----
    cudaStreamWaitEvent(D, eC, 0);
    launch_gemm(D, Pagg, WHI(3), WLO(3), nullptr, nullptr, buf0, NOP, nullptr, P2, E, H, INTC);
    launch_gemm(D, P2, WHI(4), WLO(4), rb_b1, nullptr, nullptr, NOP, nullptr, P1, E, H, H);
    launch_gemm(D, P1, WHI(5), WLO(5), rb_b2, nullptr, nullptr, P2, nullptr, P0, E, H, H);
    launch_gemm(D, P0, WHI(6), WLO(6), b_lin, nullptr, x, NOP, nullptr, P2, E, H, H);
    launch_gemm(D, P2, WHI(7), WLO(7), ra_b1, nullptr, nullptr, NOP, nullptr, P1, E, H, H);
    launch_gemm(D, P1, WHI(8), WLO(8), ra_b2, nullptr, nullptr, P2, nullptr, P0, E, H, H);
    launch_gemm(D, P0, WHI(9), WLO(9), ra_b1 + H, nullptr, nullptr, NOP, nullptr, P1, E, H, H);
    launch_gemm(D, P1, WHI(10), WLO(10), ra_b2 + H, nullptr, nullptr, P0, out, NOP, E, H, H);
}